// round 3
// baseline (speedup 1.0000x reference)
#include <cuda_runtime.h>

#define B_    2048
#define FS_   32
#define FA_   16
#define T_    512
#define H_    64
#define SQRT_DT_ 0.22360679774997896f
#define MIN_V_  (-5.0f)
#define MAX_V_  (5.0f)

typedef unsigned long long u64;

__device__ __forceinline__ u64 pack2(float lo, float hi) {
    u64 r; asm("mov.b64 %0, {%1, %2};" : "=l"(r) : "f"(lo), "f"(hi)); return r;
}
__device__ __forceinline__ float2 unpack2(u64 v) {
    float2 f; asm("mov.b64 {%0, %1}, %2;" : "=f"(f.x), "=f"(f.y) : "l"(v)); return f;
}
// packed dual fp32 FMA (sm_100+): 2 fp32 FMAs per issue slot
__device__ __forceinline__ u64 ffma2(u64 a, u64 b, u64 c) {
    u64 d; asm("fma.rn.f32x2 %0, %1, %2, %3;" : "=l"(d) : "l"(a), "l"(b), "l"(c)); return d;
}
// accurate tanh from ex2.approx + rcp.approx (~1e-7 abs err)
__device__ __forceinline__ float tanh_acc(float x) {
    float e, r;
    asm("ex2.approx.f32 %0, %1;" : "=f"(e) : "f"(x * 2.8853900817779268f)); // 2*log2(e)
    asm("rcp.approx.f32 %0, %1;" : "=f"(r) : "f"(e + 1.0f));
    return (e - 1.0f) * r;
}

// Block = 512 threads = 16 warps = 4 groups of 4 warps {f0,f1,g0,g1}.
// Each group owns 4 batch elements; each MLP is split across 2 warps along K
// (kh=0: L1 k[0:24), L2 k[0:32); kh=1: L1 k[24:48), L2 k[32:64)). The L2 split
// matches the L1 output split, so each warp consumes only the hidden half it
// produced (warp-private buffer). Every warp redundantly finalizes x from
// published partials (po_sm/eps_sm, double-buffered) -> 2 barriers/step.
__global__ void __launch_bounds__(512, 1)
sde_kernel(const float* __restrict__ a_in,   // (B, FA, T)
           const float* __restrict__ x0,     // (B, FS)
           const float* __restrict__ noise,  // (T-1, B, FS)
           const float* __restrict__ Wf1, const float* __restrict__ bf1,
           const float* __restrict__ Wf2, const float* __restrict__ bf2,
           const float* __restrict__ Wg1, const float* __restrict__ bg1,
           const float* __restrict__ Wg2, const float* __restrict__ bg2,
           float* __restrict__ out)          // (B, FS, T)
{
    const int tid  = threadIdx.x;
    const int wid  = tid >> 5;
    const int lane = tid & 31;
    const int grp  = wid >> 2;          // 0..3
    const int role = wid & 3;           // 0=f0 1=f1 2=g0 3=g1
    const int kh   = role & 1;          // k-half
    const int isG  = role >> 1;
    const int pid  = wid >> 1;          // pair id 0..7
    const int el0  = grp * 4;
    const int gb0  = blockIdx.x * 16 + el0;

    __shared__ __align__(16) float v_sm[16][4][32];          // per-warp x/h buffer (8KB)
    __shared__ __align__(16) float a_sg[2][16][4][16];       // a tiles, 4 steps, transposed (8KB)
    __shared__ __align__(16) float p1_sm[8][2][4][32];       // L1 cross-half partials (8KB)
    __shared__ __align__(16) float po_sm[2][4][4][4][32];    // L2 partials, dbl-buf (16KB)
    __shared__ __align__(16) float eps_sm[2][16][32];        // noise, dbl-buf (4KB)

    const float* W1 = isG ? Wg1 : Wf1;
    const float* B1 = isG ? bg1 : bf1;
    const float* W2 = isG ? Wg2 : Wf2;

    // ---- register-resident weight slices (80 regs) ----
    u64 w1a[12], w1b[12], w2p[16];
    const int k1b = kh * 24;
#pragma unroll
    for (int kp = 0; kp < 12; kp++) {
        const int k = k1b + 2 * kp;
        w1a[kp] = pack2(W1[k*H_ + lane],      W1[(k+1)*H_ + lane]);
        w1b[kp] = pack2(W1[k*H_ + 32 + lane], W1[(k+1)*H_ + 32 + lane]);
    }
    const int k2b = kh * 32;
#pragma unroll
    for (int kp = 0; kp < 16; kp++) {
        const int k = k2b + 2 * kp;
        w2p[kp] = pack2(W2[k*FS_ + lane], W2[(k+1)*FS_ + lane]);
    }
    const float b1h  = B1[kh * 32 + lane];
    const float bf2v = bf2[lane];
    const float bg2v = bg2[lane];

    const float* a_base = a_in + (size_t)gb0 * (FA_*T_) + (size_t)(lane >> 1) * T_ + (lane & 1) * 2;
    float*       out_b  = out  + (size_t)gb0 * (FS_*T_) + (size_t)lane * T_;

    // ---- prologue ----
#pragma unroll
    for (int e = 0; e < 4; e++) {
        float xv = x0[(size_t)(gb0 + e) * FS_ + lane];
        v_sm[wid][e][lane] = xv;
        if (role == 0) out_b[(size_t)e * (FS_*T_)] = xv;
    }
    float2 areg[4];
    if (role == 1) {
#pragma unroll
        for (int e = 0; e < 4; e++) {
            float2 v = *reinterpret_cast<const float2*>(a_base + (size_t)e * (FA_*T_));
            a_sg[0][el0 + e][(lane & 1)*2 + 0][lane >> 1] = v.x;
            a_sg[0][el0 + e][(lane & 1)*2 + 1][lane >> 1] = v.y;
        }
#pragma unroll
        for (int e = 0; e < 4; e++)
            areg[e] = *reinterpret_cast<const float2*>(a_base + (size_t)e * (FA_*T_) + 4);
    }
    __syncthreads();

    const int barP = 1 + pid;   // 64-thread pair barrier
    const int barG = 9 + grp;   // 128-thread group barrier

#pragma unroll 1
    for (int t = 1; t < T_; t++) {
        const int ai = t - 1, tb = t & 1, g4 = ai >> 2, ab = g4 & 1, sl = ai & 3;

        // g1: issue noise loads early (consumed after barG, ~800cy later)
        float eptmp[4];
        if (role == 3) {
            const float* np = noise + (size_t)ai * (B_*FS_) + (size_t)gb0 * FS_ + lane;
#pragma unroll
            for (int e = 0; e < 4; e++) eptmp[e] = np[e * FS_];
        }

        // ---------- layer 1 partials over this warp's k-half ----------
        u64 accA[4], accB[4];
#pragma unroll
        for (int e = 0; e < 4; e++) { accA[e] = 0ull; accB[e] = 0ull; }

        if (kh == 0) {
#pragma unroll
            for (int e = 0; e < 4; e++) {
                const ulonglong2* ap = reinterpret_cast<const ulonglong2*>(&a_sg[ab][el0+e][sl][0]);
                const ulonglong2* xp = reinterpret_cast<const ulonglong2*>(&v_sm[wid][e][0]);
#pragma unroll
                for (int q = 0; q < 4; q++) {           // s[0:16) = a
                    ulonglong2 v = ap[q];
                    accA[e] = ffma2(v.x, w1a[2*q],   accA[e]);
                    accA[e] = ffma2(v.y, w1a[2*q+1], accA[e]);
                    accB[e] = ffma2(v.x, w1b[2*q],   accB[e]);
                    accB[e] = ffma2(v.y, w1b[2*q+1], accB[e]);
                }
#pragma unroll
                for (int q = 0; q < 2; q++) {           // s[16:24) = x[0:8)
                    ulonglong2 v = xp[q];
                    accA[e] = ffma2(v.x, w1a[8+2*q], accA[e]);
                    accA[e] = ffma2(v.y, w1a[9+2*q], accA[e]);
                    accB[e] = ffma2(v.x, w1b[8+2*q], accB[e]);
                    accB[e] = ffma2(v.y, w1b[9+2*q], accB[e]);
                }
            }
        } else {
#pragma unroll
            for (int e = 0; e < 4; e++) {
                const ulonglong2* xp = reinterpret_cast<const ulonglong2*>(&v_sm[wid][e][8]);
#pragma unroll
                for (int q = 0; q < 6; q++) {           // s[24:48) = x[8:32)
                    ulonglong2 v = xp[q];
                    accA[e] = ffma2(v.x, w1a[2*q],   accA[e]);
                    accA[e] = ffma2(v.y, w1a[2*q+1], accA[e]);
                    accB[e] = ffma2(v.x, w1b[2*q],   accB[e]);
                    accB[e] = ffma2(v.y, w1b[2*q+1], accB[e]);
                }
            }
        }

        // horizontal sums; send the half we don't finalize, keep the other
        float pown[4];
#pragma unroll
        for (int e = 0; e < 4; e++) {
            float2 ua = unpack2(accA[e]), ub = unpack2(accB[e]);
            float pA = ua.x + ua.y, pB = ub.x + ub.y;
            pown[e] = kh ? pB : pA;
            p1_sm[pid][1 - kh][e][lane] = kh ? pA : pB;
        }
        asm volatile("bar.sync %0, 64;" :: "r"(barP) : "memory");

        // finalize our hidden half, stash in private buffer (overwrites x)
        __syncwarp();
#pragma unroll
        for (int e = 0; e < 4; e++) {
            float hv = tanh_acc(pown[e] + p1_sm[pid][kh][e][lane] + b1h);
            v_sm[wid][e][lane] = hv;
        }
        __syncwarp();

        // ---------- layer 2 partial over our own hidden half ----------
#pragma unroll
        for (int e = 0; e < 4; e++) {
            const ulonglong2* hp = reinterpret_cast<const ulonglong2*>(&v_sm[wid][e][0]);
            u64 c0 = 0ull, c1 = 0ull;
#pragma unroll
            for (int q = 0; q < 8; q++) {
                ulonglong2 v = hp[q];
                c0 = ffma2(v.x, w2p[2*q],   c0);
                c1 = ffma2(v.y, w2p[2*q+1], c1);
            }
            float2 u0 = unpack2(c0), u1 = unpack2(c1);
            po_sm[tb][grp][role][e][lane] = (u0.x + u0.y) + (u1.x + u1.y);
        }
        if (role == 3) {
#pragma unroll
            for (int e = 0; e < 4; e++) eps_sm[tb][el0 + e][lane] = eptmp[e];
        }
        asm volatile("bar.sync %0, 128;" :: "r"(barG) : "memory");

        // ---------- every warp redundantly finalizes x ----------
#pragma unroll
        for (int e = 0; e < 4; e++) {
            float of = po_sm[tb][grp][0][e][lane] + po_sm[tb][grp][1][e][lane] + bf2v;
            float og = po_sm[tb][grp][2][e][lane] + po_sm[tb][grp][3][e][lane] + bg2v;
            float xv = of + og * (eps_sm[tb][el0 + e][lane] * SQRT_DT_);
            xv = fminf(fmaxf(xv, MIN_V_), MAX_V_);
            v_sm[wid][e][lane] = xv;                    // overwrite h with new x
            if (role == 0) out_b[(size_t)e * (FS_*T_) + t] = xv;
        }

        // f1: a-tile staging (STS 1 group ahead, LDG 2 groups ahead)
        if (role == 1) {
            if (sl == 2 && g4 + 1 < 128) {
#pragma unroll
                for (int e = 0; e < 4; e++) {
                    a_sg[ab ^ 1][el0 + e][(lane & 1)*2 + 0][lane >> 1] = areg[e].x;
                    a_sg[ab ^ 1][el0 + e][(lane & 1)*2 + 1][lane >> 1] = areg[e].y;
                }
            }
            if (sl == 3 && g4 + 2 < 128) {
                const float* ap = a_base + (size_t)(g4 + 2) * 4;
#pragma unroll
                for (int e = 0; e < 4; e++)
                    areg[e] = *reinterpret_cast<const float2*>(ap + (size_t)e * (FA_*T_));
            }
        }
        __syncwarp();
    }
}

extern "C" void kernel_launch(void* const* d_in, const int* in_sizes, int n_in,
                              void* d_out, int out_size) {
    (void)in_sizes; (void)n_in; (void)out_size;
    // metadata order: ts, in_signal, x0, noise, Wf1, bf1, Wf2, bf2, Wg1, bg1, Wg2, bg2
    const float* a_in  = (const float*)d_in[1];
    const float* x0    = (const float*)d_in[2];
    const float* noise = (const float*)d_in[3];
    const float* Wf1   = (const float*)d_in[4];
    const float* bf1   = (const float*)d_in[5];
    const float* Wf2   = (const float*)d_in[6];
    const float* bf2   = (const float*)d_in[7];
    const float* Wg1   = (const float*)d_in[8];
    const float* bg1   = (const float*)d_in[9];
    const float* Wg2   = (const float*)d_in[10];
    const float* bg2   = (const float*)d_in[11];
    float* out = (float*)d_out;

    sde_kernel<<<B_ / 16, 512>>>(a_in, x0, noise,
                                 Wf1, bf1, Wf2, bf2,
                                 Wg1, bg1, Wg2, bg2,
                                 out);
}

// round 4
// speedup vs baseline: 1.3658x; 1.3658x over previous
#include <cuda_runtime.h>

#define B_    2048
#define FS_   32
#define FA_   16
#define T_    512
#define H_    64
#define SQRT_DT_ 0.22360679774997896f
#define MIN_V_  (-5.0f)
#define MAX_V_  (5.0f)

typedef unsigned long long u64;

__device__ __forceinline__ u64 pack2(float lo, float hi) {
    u64 r; asm("mov.b64 %0, {%1, %2};" : "=l"(r) : "f"(lo), "f"(hi)); return r;
}
__device__ __forceinline__ float2 unpack2(u64 v) {
    float2 f; asm("mov.b64 {%0, %1}, %2;" : "=f"(f.x), "=f"(f.y) : "l"(v)); return f;
}
// packed dual fp32 FMA (sm_100+)
__device__ __forceinline__ u64 ffma2(u64 a, u64 b, u64 c) {
    u64 d; asm("fma.rn.f32x2 %0, %1, %2, %3;" : "=l"(d) : "l"(a), "l"(b), "l"(c)); return d;
}
// accurate tanh from ex2.approx + rcp.approx (~1e-7 abs err)
__device__ __forceinline__ float tanh_acc(float x) {
    float e, r;
    asm("ex2.approx.f32 %0, %1;" : "=f"(e) : "f"(x * 2.8853900817779268f)); // 2*log2(e)
    asm("rcp.approx.f32 %0, %1;" : "=f"(r) : "f"(e + 1.0f));
    return (e - 1.0f) * r;
}

// Block = 256 threads = 8 warps = 4 (f,g) pairs; 4 batch elements per pair,
// 16 per block, grid = 128 (single wave). Full weights register-resident per
// warp. ONE named barrier per step: f publishes o_f, g publishes d; both warps
// then redundantly finalize x into their own private buffer. Pairs 2,3 are
// phase-skewed at start so SMSP co-residents interleave stall windows.
__global__ void __launch_bounds__(256, 1)
sde_kernel(const float* __restrict__ a_in,   // (B, FA, T)
           const float* __restrict__ x0,     // (B, FS)
           const float* __restrict__ noise,  // (T-1, B, FS)
           const float* __restrict__ Wf1, const float* __restrict__ bf1,
           const float* __restrict__ Wf2, const float* __restrict__ bf2,
           const float* __restrict__ Wg1, const float* __restrict__ bg1,
           const float* __restrict__ Wg2, const float* __restrict__ bg2,
           float* __restrict__ out)          // (B, FS, T)
{
    const int tid  = threadIdx.x;
    const int wid  = tid >> 5;
    const int lane = tid & 31;
    const int pair = wid >> 1;            // 0..3
    const bool is_g = (wid & 1) != 0;
    const int el0  = pair * 4;
    const int gb0  = blockIdx.x * 16 + el0;

    __shared__ __align__(16) float v_sm[8][4][64];        // per-warp x/h buffer (8KB)
    __shared__ __align__(16) float a_sg[2][16][4][16];    // a tiles, 4 steps, transposed (8KB)
    __shared__ __align__(16) float ex_sm[2][4][2][4][32]; // {o_f,d} exchange, dbl-buf (8KB)
    __shared__ float sink[8][32];                         // skew sink, never read (1KB)

    const float* W1 = is_g ? Wg1 : Wf1;
    const float* b1 = is_g ? bg1 : bf1;
    const float* W2 = is_g ? Wg2 : Wf2;
    const float* b2 = is_g ? bg2 : bf2;

    // -------- register-resident weights, packed (k, k+1) over k --------
    u64 w1a[24], w1b[24], w2p[32];
#pragma unroll
    for (int kp = 0; kp < 24; kp++) {
        w1a[kp] = pack2(W1[(2*kp)*H_ + lane],      W1[(2*kp+1)*H_ + lane]);
        w1b[kp] = pack2(W1[(2*kp)*H_ + lane + 32], W1[(2*kp+1)*H_ + lane + 32]);
    }
#pragma unroll
    for (int kp = 0; kp < 32; kp++) {
        w2p[kp] = pack2(W2[(2*kp)*FS_ + lane], W2[(2*kp+1)*FS_ + lane]);
    }
    const float bias1a = b1[lane];
    const float bias1b = b1[lane + 32];
    const float bias2  = b2[lane];

    const float* a_base  = a_in  + (size_t)gb0 * (FA_*T_) + (size_t)(lane >> 1) * T_ + (lane & 1) * 2;
    const float* nz_base = noise + (size_t)gb0 * FS_ + lane;
    float*       out_b   = out   + (size_t)gb0 * (FS_*T_) + (size_t)lane * T_;

    float2 areg[4];
    float  eps_n[4];

    // -------- prologue --------
#pragma unroll
    for (int e = 0; e < 4; e++) {
        float xv = x0[(size_t)(gb0 + e) * FS_ + lane];
        v_sm[wid][e][lane] = xv;                     // both warps keep own x copy
        if (!is_g) out_b[(size_t)e * (FS_*T_)] = xv;
    }
    if (!is_g) {
#pragma unroll
        for (int e = 0; e < 4; e++) {
            float2 v = *reinterpret_cast<const float2*>(a_base + (size_t)e * (FA_*T_));
            a_sg[0][el0 + e][(lane & 1)*2 + 0][lane >> 1] = v.x;
            a_sg[0][el0 + e][(lane & 1)*2 + 1][lane >> 1] = v.y;
        }
#pragma unroll
        for (int e = 0; e < 4; e++)
            areg[e] = *reinterpret_cast<const float2*>(a_base + (size_t)e * (FA_*T_) + 4);
    } else {
#pragma unroll
        for (int e = 0; e < 4; e++) eps_n[e] = nz_base[e * FS_];
    }
    __syncthreads();

    // -------- phase skew: pairs 2,3 burn ~1 L1-pass of real-shaped work --------
    if (pair >= 2) {
        u64 sa = 0ull, sb = 0ull;
#pragma unroll
        for (int e = 0; e < 4; e++) {
            const ulonglong2* ap = reinterpret_cast<const ulonglong2*>(&a_sg[0][el0+e][0][0]);
            const ulonglong2* xp = reinterpret_cast<const ulonglong2*>(&v_sm[wid][e][0]);
#pragma unroll
            for (int q = 0; q < 4; q++) {
                ulonglong2 v = ap[q];
                sa = ffma2(v.x, w1a[2*q],   sa);
                sa = ffma2(v.y, w1a[2*q+1], sa);
                sb = ffma2(v.x, w1b[2*q],   sb);
                sb = ffma2(v.y, w1b[2*q+1], sb);
            }
#pragma unroll
            for (int q = 0; q < 8; q++) {
                ulonglong2 v = xp[q];
                sa = ffma2(v.x, w1a[8+2*q], sa);
                sa = ffma2(v.y, w1a[9+2*q], sa);
                sb = ffma2(v.x, w1b[8+2*q], sb);
                sb = ffma2(v.y, w1b[9+2*q], sb);
            }
        }
        float2 u = unpack2(sa), v = unpack2(sb);
        sink[wid][lane] = (u.x + u.y) + (v.x + v.y);   // STS side effect keeps it
    }

    const int bar_id = 1 + pair;

#pragma unroll 1
    for (int t = 1; t < T_; t++) {
        const int ai  = t - 1;
        const int tb  = t & 1;
        const int g4  = ai >> 2;
        const int buf = g4 & 1;
        const int sl  = ai & 3;

        // g: rotate noise double-buffer; issue next load early
        float eps_u[4];
        if (is_g) {
#pragma unroll
            for (int e = 0; e < 4; e++) eps_u[e] = eps_n[e];
            if (t < T_ - 1) {
                const float* np = nz_base + (size_t)t * (B_ * FS_);
#pragma unroll
                for (int e = 0; e < 4; e++) eps_n[e] = np[e * FS_];
            }
        }

        // ---------------- layer 1 (48 -> 64), 8 chains ----------------
        u64 aa[4], ab[4];
#pragma unroll
        for (int e = 0; e < 4; e++) { aa[e] = 0ull; ab[e] = 0ull; }
#pragma unroll
        for (int e = 0; e < 4; e++) {
            const ulonglong2* ap = reinterpret_cast<const ulonglong2*>(&a_sg[buf][el0+e][sl][0]);
            const ulonglong2* xp = reinterpret_cast<const ulonglong2*>(&v_sm[wid][e][0]);
#pragma unroll
            for (int q = 0; q < 4; q++) {            // s[0:16) = a_t
                ulonglong2 v = ap[q];
                aa[e] = ffma2(v.x, w1a[2*q],   aa[e]);
                aa[e] = ffma2(v.y, w1a[2*q+1], aa[e]);
                ab[e] = ffma2(v.x, w1b[2*q],   ab[e]);
                ab[e] = ffma2(v.y, w1b[2*q+1], ab[e]);
            }
#pragma unroll
            for (int q = 0; q < 8; q++) {            // s[16:48) = x_t
                ulonglong2 v = xp[q];
                aa[e] = ffma2(v.x, w1a[8+2*q], aa[e]);
                aa[e] = ffma2(v.y, w1a[9+2*q], aa[e]);
                ab[e] = ffma2(v.x, w1b[8+2*q], ab[e]);
                ab[e] = ffma2(v.y, w1b[9+2*q], ab[e]);
            }
        }
        // tanh + stash h in private buffer (overwrites x)
#pragma unroll
        for (int e = 0; e < 4; e++) {
            float2 u = unpack2(aa[e]);
            float2 v = unpack2(ab[e]);
            v_sm[wid][e][lane]      = tanh_acc(u.x + u.y + bias1a);
            v_sm[wid][e][lane + 32] = tanh_acc(v.x + v.y + bias1b);
        }
        __syncwarp();

        // ---------------- layer 2 (64 -> 32), 8 chains ----------------
        float o[4];
#pragma unroll
        for (int e = 0; e < 4; e++) {
            const ulonglong2* hp = reinterpret_cast<const ulonglong2*>(&v_sm[wid][e][0]);
            u64 c0 = 0ull, c1 = 0ull;
#pragma unroll
            for (int q = 0; q < 16; q++) {
                ulonglong2 v = hp[q];
                c0 = ffma2(v.x, w2p[2*q],   c0);
                c1 = ffma2(v.y, w2p[2*q+1], c1);
            }
            float2 u0 = unpack2(c0), u1 = unpack2(c1);
            o[e] = (u0.x + u0.y) + (u1.x + u1.y) + bias2;
        }

        // publish: f -> o_f (incl. bias), g -> full diffusion term d
        if (!is_g) {
#pragma unroll
            for (int e = 0; e < 4; e++) ex_sm[tb][pair][0][e][lane] = o[e];
        } else {
#pragma unroll
            for (int e = 0; e < 4; e++) ex_sm[tb][pair][1][e][lane] = o[e] * (eps_u[e] * SQRT_DT_);
        }

        // f: a-tile staging moved pre-barrier (fills partner-wait window)
        if (!is_g) {
            if (sl == 2 && g4 + 1 < 128) {
#pragma unroll
                for (int e = 0; e < 4; e++) {
                    a_sg[buf ^ 1][el0 + e][(lane & 1)*2 + 0][lane >> 1] = areg[e].x;
                    a_sg[buf ^ 1][el0 + e][(lane & 1)*2 + 1][lane >> 1] = areg[e].y;
                }
            }
            if (sl == 3 && g4 + 2 < 128) {
                const float* ap = a_base + (size_t)(g4 + 2) * 4;
#pragma unroll
                for (int e = 0; e < 4; e++)
                    areg[e] = *reinterpret_cast<const float2*>(ap + (size_t)e * (FA_*T_));
            }
        }

        asm volatile("bar.sync %0, 64;" :: "r"(bar_id) : "memory");

        // both warps redundantly finalize x into their own buffer
#pragma unroll
        for (int e = 0; e < 4; e++) {
            float xv = ex_sm[tb][pair][0][e][lane] + ex_sm[tb][pair][1][e][lane];
            xv = fminf(fmaxf(xv, MIN_V_), MAX_V_);
            v_sm[wid][e][lane] = xv;                  // overwrite h with new x
            if (!is_g) out_b[(size_t)e * (FS_*T_) + t] = xv;
        }
        __syncwarp();
    }
}

extern "C" void kernel_launch(void* const* d_in, const int* in_sizes, int n_in,
                              void* d_out, int out_size) {
    (void)in_sizes; (void)n_in; (void)out_size;
    // metadata order: ts, in_signal, x0, noise, Wf1, bf1, Wf2, bf2, Wg1, bg1, Wg2, bg2
    const float* a_in  = (const float*)d_in[1];
    const float* x0    = (const float*)d_in[2];
    const float* noise = (const float*)d_in[3];
    const float* Wf1   = (const float*)d_in[4];
    const float* bf1   = (const float*)d_in[5];
    const float* Wf2   = (const float*)d_in[6];
    const float* bf2   = (const float*)d_in[7];
    const float* Wg1   = (const float*)d_in[8];
    const float* bg1   = (const float*)d_in[9];
    const float* Wg2   = (const float*)d_in[10];
    const float* bg2   = (const float*)d_in[11];
    float* out = (float*)d_out;

    sde_kernel<<<B_ / 16, 256>>>(a_in, x0, noise,
                                 Wf1, bf1, Wf2, bf2,
                                 Wg1, bg1, Wg2, bg2,
                                 out);
}